// round 1
// baseline (speedup 1.0000x reference)
#include <cuda_runtime.h>
#include <cuda_bf16.h>

// PresetEmbedding: out[n,l,h] =
//   l odd : cat_table[easy[round(64*u[n,l,2] + u[n,l,0])]][h] + pe[l,h]
//   l even: 2*(u[n,l,1]-0.5) * w_num[num_param_types[l/2]*H + h] + pe[l,h]
// pe[l,h] = sin(l / 10000^(h_pair/128)) for even h, cos(...) for odd h, h_pair = h/2.
//
// N=512, L=512, H=256. Output 512*512*256 fp32 = 268 MB -> HBM-write-bound.

#define N_BATCH 512
#define L_SEQ   512
#define H_DIM   256

// Precomputed positional embedding (512 KB) — recomputed every launch (cheap),
// stays L2-resident for the main kernel.
__device__ float d_pe[L_SEQ * H_DIM];

__global__ void pe_kernel() {
    int i = blockIdx.x * blockDim.x + threadIdx.x;   // 0 .. 131071
    int l = i >> 8;          // sequence position
    int h = i & 255;         // hidden index
    int j = h >> 1;          // frequency index 0..127
    // omega_inv = 10000^(j/128); ang = l * 10000^(-j/128)
    // log2(10000)/128 = 13.287712379549449 / 128
    const float c = 0.10381025296522851f;            // log2(1e4)/128
    float ang = (float)l * exp2f(-(float)j * c);
    d_pe[i] = (h & 1) ? cosf(ang) : sinf(ang);
}

__global__ __launch_bounds__(256, 8)
void embed_kernel(const float* __restrict__ u,          // (N, L, 3)
                  const float* __restrict__ w_num,      // (T*H,) viewed (T, H)
                  const float* __restrict__ cat_table,  // (n_emb, H)
                  const int*   __restrict__ easy,       // (MAXC*T,)
                  const int*   __restrict__ num_types,  // (L/2,)
                  float*       __restrict__ out)        // (N, L, H)
{
    int tid = blockIdx.x * 256 + threadIdx.x;  // 0 .. N*L*64 - 1
    int row = tid >> 6;                        // n*L + l
    int h4  = (tid & 63) << 2;                 // h offset (float4 granularity)
    int l   = row & (L_SEQ - 1);

    const float4 pe = *reinterpret_cast<const float4*>(&d_pe[l * H_DIM + h4]);
    const float* ub = u + (size_t)row * 3;

    float4 r;
    if (l & 1) {
        // categorical row: table lookup
        float u0 = __ldg(ub + 0);
        float u2 = __ldg(ub + 2);
        int big  = __float2int_rn(u2 * 64.0f + u0);
        int idx  = __ldg(easy + big);
        const float4 t = *reinterpret_cast<const float4*>(&cat_table[(size_t)idx * H_DIM + h4]);
        r.x = t.x + pe.x;
        r.y = t.y + pe.y;
        r.z = t.z + pe.z;
        r.w = t.w + pe.w;
    } else {
        // numeric row: scaled weight row
        float v  = 2.0f * (__ldg(ub + 1) - 0.5f);
        int   pt = __ldg(num_types + (l >> 1));
        const float4 w = *reinterpret_cast<const float4*>(&w_num[(size_t)pt * H_DIM + h4]);
        r.x = fmaf(v, w.x, pe.x);
        r.y = fmaf(v, w.y, pe.y);
        r.z = fmaf(v, w.z, pe.z);
        r.w = fmaf(v, w.w, pe.w);
    }

    // Streaming store: keep L2 for the hot tables, output is write-once.
    __stcs(reinterpret_cast<float4*>(&out[(size_t)row * H_DIM + h4]), r);
}

extern "C" void kernel_launch(void* const* d_in, const int* in_sizes, int n_in,
                              void* d_out, int out_size) {
    // metadata order: u_in, w_num, cat_table, cat_rows, num_rows, num_param_types, easy_index
    const float* u         = (const float*)d_in[0];
    const float* w_num     = (const float*)d_in[1];
    const float* cat_table = (const float*)d_in[2];
    // d_in[3] = cat_rows (odd l), d_in[4] = num_rows (even l) — pattern is hardcoded
    const int*   num_types = (const int*)d_in[5];
    const int*   easy      = (const int*)d_in[6];
    float* out = (float*)d_out;

    pe_kernel<<<(L_SEQ * H_DIM) / 256, 256>>>();

    int total_f4 = N_BATCH * L_SEQ * (H_DIM / 4);   // 16,777,216 threads
    embed_kernel<<<total_f4 / 256, 256>>>(u, w_num, cat_table, easy, num_types, out);
}

// round 2
// speedup vs baseline: 1.2375x; 1.2375x over previous
#include <cuda_runtime.h>
#include <cuda_bf16.h>

// PresetEmbedding: out[n,l,h] =
//   l odd : cat_table[easy[round(64*u[n,l,2] + u[n,l,0])]][h] + pe[l,h]
//   l even: 2*(u[n,l,1]-0.5) * w_num[num_param_types[l/2]*H + h] + pe[l,h]
// N=512, L=512, H=256. Output 268 MB fp32 -> HBM-write-bound target (~41us floor).
//
// R2 design: one block per (l, n-chunk). All l-dependent vectors (pe row, w row)
// are hoisted into registers; inner loop over n issues only the per-n loads +
// stores. Cuts LSU instruction count ~3x vs R1 (which was issue-limited at
// DRAM=36%, L1=57%).

#define N_BATCH 512
#define L_SEQ   512
#define H_DIM   256
#define NSPLIT  8                        // grid.y: n-chunks of 64
#define NCHUNK  (N_BATCH / NSPLIT)       // 64

__device__ float d_pe[L_SEQ * H_DIM];

__global__ void pe_kernel() {
    int i = blockIdx.x * blockDim.x + threadIdx.x;   // 0 .. 131071
    int l = i >> 8;
    int h = i & 255;
    int j = h >> 1;                                   // freq index 0..127
    const float c = 0.10381025296522851f;             // log2(1e4)/128
    float ang = (float)l * exp2f(-(float)j * c);
    d_pe[i] = (h & 1) ? cosf(ang) : sinf(ang);
}

__global__ __launch_bounds__(256)
void embed_kernel(const float* __restrict__ u,          // (N, L, 3)
                  const float* __restrict__ w_num,      // (T, H)
                  const float* __restrict__ cat_table,  // (n_emb, H)
                  const int*   __restrict__ easy,       // (MAXC*T,)
                  const int*   __restrict__ num_types,  // (L/2,)
                  float*       __restrict__ out)        // (N, L, H)
{
    const int l     = blockIdx.x;                       // 0..511 (block-uniform)
    const int nbase = blockIdx.y * NCHUNK;
    const int ht    = threadIdx.x & 15;                 // h-thread: 4 float4s each
    const int nsub  = threadIdx.x >> 4;                 // 0..15

    // Hoist positional-embedding row into registers (block-invariant).
    float4 pe[4];
    #pragma unroll
    for (int k = 0; k < 4; k++)
        pe[k] = *reinterpret_cast<const float4*>(&d_pe[l * H_DIM + (ht + 16 * k) * 4]);

    if (l & 1) {
        // ---- categorical rows: table lookup per n ----
        #pragma unroll
        for (int it = 0; it < NCHUNK / 16; it++) {
            int n = nbase + it * 16 + nsub;
            const float* ub = u + ((size_t)n * L_SEQ + l) * 3;
            float u0 = __ldg(ub + 0);
            float u2 = __ldg(ub + 2);
            int big  = __float2int_rn(u2 * 64.0f + u0);
            int idx  = __ldg(easy + big);
            const float* trow = cat_table + (size_t)idx * H_DIM;
            float*       orow = out + ((size_t)n * L_SEQ + l) * H_DIM;
            #pragma unroll
            for (int k = 0; k < 4; k++) {
                float4 t = *reinterpret_cast<const float4*>(&trow[(ht + 16 * k) * 4]);
                float4 r;
                r.x = t.x + pe[k].x;
                r.y = t.y + pe[k].y;
                r.z = t.z + pe[k].z;
                r.w = t.w + pe[k].w;
                __stcs(reinterpret_cast<float4*>(&orow[(ht + 16 * k) * 4]), r);
            }
        }
    } else {
        // ---- numeric rows: v * w + pe, w row block-invariant ----
        int pt = __ldg(num_types + (l >> 1));
        const float* wrow = w_num + (size_t)pt * H_DIM;
        float4 w[4];
        #pragma unroll
        for (int k = 0; k < 4; k++)
            w[k] = *reinterpret_cast<const float4*>(&wrow[(ht + 16 * k) * 4]);

        #pragma unroll
        for (int it = 0; it < NCHUNK / 16; it++) {
            int n = nbase + it * 16 + nsub;
            const float* ub = u + ((size_t)n * L_SEQ + l) * 3;
            float v = 2.0f * (__ldg(ub + 1) - 0.5f);
            float*  orow = out + ((size_t)n * L_SEQ + l) * H_DIM;
            #pragma unroll
            for (int k = 0; k < 4; k++) {
                float4 r;
                r.x = fmaf(v, w[k].x, pe[k].x);
                r.y = fmaf(v, w[k].y, pe[k].y);
                r.z = fmaf(v, w[k].z, pe[k].z);
                r.w = fmaf(v, w[k].w, pe[k].w);
                __stcs(reinterpret_cast<float4*>(&orow[(ht + 16 * k) * 4]), r);
            }
        }
    }
}

extern "C" void kernel_launch(void* const* d_in, const int* in_sizes, int n_in,
                              void* d_out, int out_size) {
    // metadata order: u_in, w_num, cat_table, cat_rows, num_rows, num_param_types, easy_index
    const float* u         = (const float*)d_in[0];
    const float* w_num     = (const float*)d_in[1];
    const float* cat_table = (const float*)d_in[2];
    const int*   num_types = (const int*)d_in[5];
    const int*   easy      = (const int*)d_in[6];
    float* out = (float*)d_out;

    pe_kernel<<<(L_SEQ * H_DIM) / 256, 256>>>();

    dim3 grid(L_SEQ, NSPLIT);
    embed_kernel<<<grid, 256>>>(u, w_num, cat_table, easy, num_types, out);
}